// round 2
// baseline (speedup 1.0000x reference)
#include <cuda_runtime.h>

#define N_NODES 100000
#define N_EDGES 3200000
#define F_IN    512
#define F_HID   256
#define N_CLASS 41

#define SCAN_B   1024
#define N_SCAN_BLK ((N_NODES + SCAN_B - 1) / SCAN_B)   // 98

// ---------------- scratch (device globals; no allocation allowed) ------------
__device__ float g_h1[(size_t)N_NODES * F_HID];   // x @ W1
__device__ float g_a1[(size_t)N_NODES * F_HID];   // relu(agg(h1)+b1)
__device__ float g_h2[(size_t)N_NODES * N_CLASS]; // a1 @ W2
__device__ float g_dinv[N_NODES];
__device__ int   g_cnt[N_NODES];
__device__ int   g_rowptr[N_NODES];
__device__ int   g_cursor[N_NODES];
__device__ int   g_srcs[N_EDGES];
__device__ int   g_bsums[128];
__device__ int   g_is32;          // 1 if edge_index is int32, 0 if int64

// ---------------- edge dtype detection ---------------------------------------
// Read the edge buffer as int32. Under either true dtype, reading the first
// 2*N_EDGES int32 words never exceeds the buffer. If the data is int64
// (values < 2^31, little-endian), every odd word is a zero high-half. If the
// data is int32, odd words are real edge values (mostly nonzero). Any nonzero
// odd word => int32 layout.
__global__ void k_detect(const int* __restrict__ ei32) {
    int i = blockIdx.x * blockDim.x + threadIdx.x;
    if (i < N_EDGES) {
        if (ei32[2 * i + 1] != 0) g_is32 = 1;
    }
}

__device__ __forceinline__ int edge_val(const void* ei, int half, int e) {
    if (g_is32) return ((const int*)ei)[(size_t)half * N_EDGES + e];
    return (int)((const long long*)ei)[(size_t)half * N_EDGES + e];
}

// ---------------- CSR build --------------------------------------------------
__global__ void k_zero_cnt() {
    int i = blockIdx.x * blockDim.x + threadIdx.x;
    if (i < N_NODES) g_cnt[i] = 0;
    if (i == 0) g_is32 = 0;
}

__global__ void k_count(const void* __restrict__ ei) {
    int e = blockIdx.x * blockDim.x + threadIdx.x;
    if (e < N_EDGES) {
        int d = edge_val(ei, 1, e);
        if ((unsigned)d < N_NODES) atomicAdd(&g_cnt[d], 1);
    }
}

__global__ void k_scan_block() {
    __shared__ int sh[SCAN_B];
    int idx = blockIdx.x * SCAN_B + threadIdx.x;
    int v = (idx < N_NODES) ? g_cnt[idx] : 0;
    sh[threadIdx.x] = v;
    __syncthreads();
    for (int off = 1; off < SCAN_B; off <<= 1) {
        int t = (threadIdx.x >= off) ? sh[threadIdx.x - off] : 0;
        __syncthreads();
        sh[threadIdx.x] += t;
        __syncthreads();
    }
    if (idx < N_NODES) g_rowptr[idx] = sh[threadIdx.x] - v;  // exclusive within block
    if (threadIdx.x == SCAN_B - 1) g_bsums[blockIdx.x] = sh[SCAN_B - 1];
}

__global__ void k_scan_sums() {
    int run = 0;
    for (int b = 0; b < N_SCAN_BLK; b++) {
        int t = g_bsums[b];
        g_bsums[b] = run;
        run += t;
    }
}

__global__ void k_scan_finish() {
    int i = blockIdx.x * blockDim.x + threadIdx.x;
    if (i < N_NODES) {
        int rp = g_rowptr[i] + g_bsums[i >> 10];
        g_rowptr[i] = rp;
        g_cursor[i] = rp;
        g_dinv[i]   = rsqrtf((float)(g_cnt[i] + 1));  // +1 self loop
    }
}

__global__ void k_scatter(const void* __restrict__ ei) {
    int e = blockIdx.x * blockDim.x + threadIdx.x;
    if (e < N_EDGES) {
        int s = edge_val(ei, 0, e);
        int d = edge_val(ei, 1, e);
        if ((unsigned)s < N_NODES && (unsigned)d < N_NODES) {
            int pos = atomicAdd(&g_cursor[d], 1);
            g_srcs[pos] = s;
        }
    }
}

// ---------------- GEMM1: C[M,256] = A[M,512] @ B[512,256] --------------------
#define BM 128
#define BN 64
#define BK 16
__global__ void k_gemm1(const float* __restrict__ A, const float* __restrict__ B) {
    __shared__ float sA[BK][BM + 4];
    __shared__ float sB[BK][BN];

    int tid = threadIdx.x;           // 256 threads
    int tx = tid % 16, ty = tid / 16;
    int bm0 = blockIdx.x * BM;
    int bn0 = blockIdx.y * BN;

    float acc[8][4];
#pragma unroll
    for (int i = 0; i < 8; i++)
#pragma unroll
        for (int j = 0; j < 4; j++) acc[i][j] = 0.f;

    int lr = tid / 4, lc4 = (tid % 4) * 4;   // A load: 64 rows x (4 x float4)
    int br = tid / 16, bc4 = (tid % 16) * 4; // B load: 16 rows x (16 x float4)

    for (int k0 = 0; k0 < F_IN; k0 += BK) {
        // load A tile (two 64-row halves), store transposed
#pragma unroll
        for (int it = 0; it < 2; it++) {
            int grow = bm0 + it * 64 + lr;
            float4 a = make_float4(0.f, 0.f, 0.f, 0.f);
            if (grow < N_NODES)
                a = *(const float4*)&A[(size_t)grow * F_IN + k0 + lc4];
            sA[lc4 + 0][it * 64 + lr] = a.x;
            sA[lc4 + 1][it * 64 + lr] = a.y;
            sA[lc4 + 2][it * 64 + lr] = a.z;
            sA[lc4 + 3][it * 64 + lr] = a.w;
        }
        // load B tile
        *(float4*)&sB[br][bc4] = *(const float4*)&B[(size_t)(k0 + br) * F_HID + bn0 + bc4];
        __syncthreads();

#pragma unroll
        for (int k = 0; k < BK; k++) {
            float ra[8], rb[4];
#pragma unroll
            for (int i = 0; i < 8; i++) ra[i] = sA[k][ty * 8 + i];
#pragma unroll
            for (int j = 0; j < 4; j++) rb[j] = sB[k][tx * 4 + j];
#pragma unroll
            for (int i = 0; i < 8; i++)
#pragma unroll
                for (int j = 0; j < 4; j++) acc[i][j] += ra[i] * rb[j];
        }
        __syncthreads();
    }

#pragma unroll
    for (int i = 0; i < 8; i++) {
        int row = bm0 + ty * 8 + i;
        if (row < N_NODES) {
            float* c = &g_h1[(size_t)row * F_HID + bn0 + tx * 4];
#pragma unroll
            for (int j = 0; j < 4; j++) c[j] = acc[i][j];
        }
    }
}

// ---------------- Aggregation layer 1 (+bias, +relu) -------------------------
__global__ void k_agg1(const float* __restrict__ b1) {
    int warp = (blockIdx.x * blockDim.x + threadIdx.x) >> 5;
    int lane = threadIdx.x & 31;
    if (warp >= N_NODES) return;
    int d = warp;
    int start = g_rowptr[d];
    int len   = g_cursor[d] - start;   // actual scattered count (guards may drop)
    float dd  = g_dinv[d];

    float acc[8];
#pragma unroll
    for (int g = 0; g < 8; g++) acc[g] = 0.f;

    int s_next = (len > 0) ? g_srcs[start] : 0;
    for (int e = 0; e < len; e++) {
        int s = s_next;
        if (e + 1 < len) s_next = g_srcs[start + e + 1];
        float w = g_dinv[s] * dd;
        const float* row = &g_h1[(size_t)s * F_HID];
#pragma unroll
        for (int g = 0; g < 8; g++) acc[g] += w * __ldg(&row[g * 32 + lane]);
    }

    const float* rowd = &g_h1[(size_t)d * F_HID];
    float wd = dd * dd;
#pragma unroll
    for (int g = 0; g < 8; g++) {
        float v = acc[g] + wd * rowd[g * 32 + lane] + b1[g * 32 + lane];
        g_a1[(size_t)d * F_HID + g * 32 + lane] = fmaxf(v, 0.f);
    }
}

// ---------------- GEMM2: h2[M,41] = a1[M,256] @ W2[256,41] -------------------
__global__ void k_gemm2(const float* __restrict__ W2) {
    __shared__ float sW[F_HID * N_CLASS];   // 41984 B
    for (int i = threadIdx.x; i < F_HID * N_CLASS; i += blockDim.x)
        sW[i] = W2[i];
    __syncthreads();

    int lane = threadIdx.x & 31;
    int row  = blockIdx.x * 8 + (threadIdx.x >> 5);
    if (row >= N_NODES) return;

    float acc0 = 0.f, acc1 = 0.f;
    const float* a = &g_a1[(size_t)row * F_HID];
    for (int k0 = 0; k0 < F_HID; k0 += 32) {
        float av = a[k0 + lane];
#pragma unroll
        for (int j = 0; j < 32; j++) {
            float aj = __shfl_sync(0xffffffffu, av, j);
            const float* w = &sW[(k0 + j) * N_CLASS];
            acc0 += aj * w[lane];
            if (lane < N_CLASS - 32) acc1 += aj * w[lane + 32];
        }
    }
    g_h2[(size_t)row * N_CLASS + lane] = acc0;
    if (lane < N_CLASS - 32) g_h2[(size_t)row * N_CLASS + 32 + lane] = acc1;
}

// ---------------- Aggregation layer 2 + bias + log_softmax -------------------
__global__ void k_agg2_softmax(const float* __restrict__ b2, float* __restrict__ out) {
    int warp = (blockIdx.x * blockDim.x + threadIdx.x) >> 5;
    int lane = threadIdx.x & 31;
    if (warp >= N_NODES) return;
    int d = warp;
    int start = g_rowptr[d];
    int len   = g_cursor[d] - start;
    float dd  = g_dinv[d];
    bool hi   = lane < (N_CLASS - 32);   // lanes 0..8 own col lane+32

    float acc0 = 0.f, acc1 = 0.f;
    int s_next = (len > 0) ? g_srcs[start] : 0;
    for (int e = 0; e < len; e++) {
        int s = s_next;
        if (e + 1 < len) s_next = g_srcs[start + e + 1];
        float w = g_dinv[s] * dd;
        const float* row = &g_h2[(size_t)s * N_CLASS];
        acc0 += w * __ldg(&row[lane]);
        if (hi) acc1 += w * __ldg(&row[lane + 32]);
    }
    const float* rowd = &g_h2[(size_t)d * N_CLASS];
    float wd = dd * dd;
    float v0 = acc0 + wd * rowd[lane] + b2[lane];
    float v1 = hi ? (acc1 + wd * rowd[lane + 32] + b2[lane + 32]) : -1e30f;

    // log_softmax across the 41 values
    float m = fmaxf(v0, v1);
#pragma unroll
    for (int o = 16; o > 0; o >>= 1) m = fmaxf(m, __shfl_xor_sync(0xffffffffu, m, o));
    float se = expf(v0 - m) + (hi ? expf(v1 - m) : 0.f);
#pragma unroll
    for (int o = 16; o > 0; o >>= 1) se += __shfl_xor_sync(0xffffffffu, se, o);
    float lse = m + logf(se);

    out[(size_t)d * N_CLASS + lane] = v0 - lse;
    if (hi) out[(size_t)d * N_CLASS + 32 + lane] = v1 - lse;
}

// ---------------- launch -----------------------------------------------------
extern "C" void kernel_launch(void* const* d_in, const int* in_sizes, int n_in,
                              void* d_out, int out_size) {
    const float* x  = (const float*)d_in[0];
    const void*  ei = d_in[1];                 // int32 or int64, detected on device
    const float* W1 = (const float*)d_in[2];
    const float* b1 = (const float*)d_in[3];
    const float* W2 = (const float*)d_in[4];
    const float* b2 = (const float*)d_in[5];
    float* out = (float*)d_out;

    // CSR build (with edge-dtype detection)
    k_zero_cnt<<<(N_NODES + 255) / 256, 256>>>();
    k_detect<<<(N_EDGES + 255) / 256, 256>>>((const int*)ei);
    k_count<<<(N_EDGES + 255) / 256, 256>>>(ei);
    k_scan_block<<<N_SCAN_BLK, SCAN_B>>>();
    k_scan_sums<<<1, 1>>>();
    k_scan_finish<<<(N_NODES + 255) / 256, 256>>>();
    k_scatter<<<(N_EDGES + 255) / 256, 256>>>(ei);

    // layer 1
    {
        dim3 grid((N_NODES + BM - 1) / BM, F_HID / BN);
        k_gemm1<<<grid, 256>>>(x, W1);
    }
    k_agg1<<<(N_NODES * 32 + 255) / 256, 256>>>(b1);

    // layer 2
    k_gemm2<<<(N_NODES + 7) / 8, 256>>>(W2);
    k_agg2_softmax<<<(N_NODES * 32 + 255) / 256, 256>>>(b2, out);
}

// round 4
// speedup vs baseline: 1.5923x; 1.5923x over previous
#include <cuda_runtime.h>
#include <cstdint>

#define N_NODES 100000
#define N_EDGES 3200000
#define F_IN    512
#define F_HID   256
#define N_CLASS 41

#define SCAN_B   1024
#define N_SCAN_BLK ((N_NODES + SCAN_B - 1) / SCAN_B)   // 98

// ---------------- scratch (device globals; no allocation allowed) ------------
__device__ __align__(256) float g_h1[(size_t)N_NODES * F_HID];   // x @ W1 (fp32)
__device__ __align__(256) float g_h2[(size_t)N_NODES * N_CLASS]; // per-node logits pre-agg
__device__ __align__(256) float g_dinv[N_NODES];
__device__ __align__(256) float g_wsrc[N_EDGES];                 // dinv[src] per CSR slot
__device__ int   g_cnt[N_NODES];
__device__ int   g_rowptr[N_NODES];
__device__ int   g_cursor[N_NODES];
__device__ __align__(256) int g_srcs[N_EDGES];
__device__ int   g_bsums[128];
__device__ int   g_is32;          // 1 if edge_index is int32, 0 if int64

// ---------------- edge dtype detection ---------------------------------------
// Reading the first 2*N_EDGES int32 words never exceeds the buffer under either
// dtype. int64 (values < 2^31, LE): every odd word is a zero high-half.
// int32: odd words are real edge values (mostly nonzero).
__global__ void k_detect(const int* __restrict__ ei32) {
    int i = blockIdx.x * blockDim.x + threadIdx.x;
    if (i < N_EDGES) {
        if (ei32[2 * i + 1] != 0) g_is32 = 1;
    }
}

__device__ __forceinline__ int edge_val(const void* ei, int half, int e) {
    if (g_is32) return ((const int*)ei)[(size_t)half * N_EDGES + e];
    return (int)((const long long*)ei)[(size_t)half * N_EDGES + e];
}

// ---------------- CSR build --------------------------------------------------
__global__ void k_zero_cnt() {
    int i = blockIdx.x * blockDim.x + threadIdx.x;
    if (i < N_NODES) g_cnt[i] = 0;
    if (i == 0) g_is32 = 0;
}

__global__ void k_count(const void* __restrict__ ei) {
    int e = blockIdx.x * blockDim.x + threadIdx.x;
    if (e < N_EDGES) {
        int d = edge_val(ei, 1, e);
        if ((unsigned)d < N_NODES) atomicAdd(&g_cnt[d], 1);
    }
}

__global__ void k_scan_block() {
    __shared__ int sh[SCAN_B];
    int idx = blockIdx.x * SCAN_B + threadIdx.x;
    int v = (idx < N_NODES) ? g_cnt[idx] : 0;
    sh[threadIdx.x] = v;
    __syncthreads();
    for (int off = 1; off < SCAN_B; off <<= 1) {
        int t = (threadIdx.x >= off) ? sh[threadIdx.x - off] : 0;
        __syncthreads();
        sh[threadIdx.x] += t;
        __syncthreads();
    }
    if (idx < N_NODES) g_rowptr[idx] = sh[threadIdx.x] - v;  // exclusive within block
    if (threadIdx.x == SCAN_B - 1) g_bsums[blockIdx.x] = sh[SCAN_B - 1];
}

__global__ void k_scan_sums() {
    int run = 0;
    for (int b = 0; b < N_SCAN_BLK; b++) {
        int t = g_bsums[b];
        g_bsums[b] = run;
        run += t;
    }
}

__global__ void k_scan_finish() {
    int i = blockIdx.x * blockDim.x + threadIdx.x;
    if (i < N_NODES) {
        int rp = g_rowptr[i] + g_bsums[i >> 10];
        g_rowptr[i] = rp;
        g_cursor[i] = rp;
        g_dinv[i]   = rsqrtf((float)(g_cnt[i] + 1));  // +1 self loop
    }
}

__global__ void k_scatter(const void* __restrict__ ei) {
    int e = blockIdx.x * blockDim.x + threadIdx.x;
    if (e < N_EDGES) {
        int s = edge_val(ei, 0, e);
        int d = edge_val(ei, 1, e);
        if ((unsigned)s < N_NODES && (unsigned)d < N_NODES) {
            int pos = atomicAdd(&g_cursor[d], 1);
            g_srcs[pos] = s;
            g_wsrc[pos] = g_dinv[s];
        }
    }
}

// ---------------- GEMM1 (tf32 tensor cores) ----------------------------------
// C[M=100000,256] = A[M,512] @ B[512,256], tf32 mma.sync.m16n8k8, fp32 accum.
// Block tile 128x128 (grid 782x2), 8 warps, warp tile 32x64, BK=32.
#define G1_BM 128
#define G1_BN 128
#define G1_BK 32
#define SA_STRIDE 36    // banks (4m + k) all distinct for fragment loads
#define SB_STRIDE 136   // banks (8k + n) all distinct for fragment loads

__device__ __forceinline__ unsigned f2tf(float f) {
    unsigned u;
    asm("cvt.rna.tf32.f32 %0, %1;" : "=r"(u) : "f"(f));
    return u;
}

__global__ void __launch_bounds__(256, 2)
k_gemm1_tf32(const float* __restrict__ A, const float* __restrict__ B) {
    __shared__ float sA[G1_BM * SA_STRIDE];
    __shared__ float sB[G1_BK * SB_STRIDE];

    int tid  = threadIdx.x;
    int lane = tid & 31;
    int wid  = tid >> 5;
    int warp_m = wid & 3;        // 0..3 -> 32-row slice
    int warp_n = wid >> 2;       // 0..1 -> 64-col slice
    int bm0 = blockIdx.x * G1_BM;
    int bn0 = blockIdx.y * G1_BN;

    int gid = lane >> 2;         // 0..7
    int tig = lane & 3;          // 0..3

    float acc[2][8][4];
#pragma unroll
    for (int mi = 0; mi < 2; mi++)
#pragma unroll
        for (int ni = 0; ni < 8; ni++)
#pragma unroll
            for (int j = 0; j < 4; j++) acc[mi][ni][j] = 0.f;

    int ar  = tid >> 3;          // 0..31
    int ac4 = (tid & 7) * 4;     // 0..28
    int bk  = tid >> 5;          // 0..7
    int bc4 = (tid & 31) * 4;    // 0..124

    for (int k0 = 0; k0 < F_IN; k0 += G1_BK) {
        // A tile: 128 rows x 32 k  (4 rounds of 32 rows)
#pragma unroll
        for (int r4 = 0; r4 < 4; r4++) {
            int row = ar + 32 * r4;
            int gm = bm0 + row;
            float4 a = make_float4(0.f, 0.f, 0.f, 0.f);
            if (gm < N_NODES)
                a = *(const float4*)&A[(size_t)gm * F_IN + k0 + ac4];
            uint4 t;
            t.x = f2tf(a.x); t.y = f2tf(a.y); t.z = f2tf(a.z); t.w = f2tf(a.w);
            *(uint4*)&sA[row * SA_STRIDE + ac4] = t;
        }
        // B tile: 32 k x 128 n  (4 rounds of 8 k-rows)
#pragma unroll
        for (int r4 = 0; r4 < 4; r4++) {
            int k = bk + 8 * r4;
            float4 b = *(const float4*)&B[(size_t)(k0 + k) * F_HID + bn0 + bc4];
            uint4 t;
            t.x = f2tf(b.x); t.y = f2tf(b.y); t.z = f2tf(b.z); t.w = f2tf(b.w);
            *(uint4*)&sB[k * SB_STRIDE + bc4] = t;
        }
        __syncthreads();

#pragma unroll
        for (int kk = 0; kk < G1_BK; kk += 8) {
            unsigned af[2][4];
#pragma unroll
            for (int mi = 0; mi < 2; mi++) {
                int mb = warp_m * 32 + mi * 16;
                af[mi][0] = __float_as_uint(sA[(mb + gid)     * SA_STRIDE + kk + tig]);
                af[mi][1] = __float_as_uint(sA[(mb + 8 + gid) * SA_STRIDE + kk + tig]);
                af[mi][2] = __float_as_uint(sA[(mb + gid)     * SA_STRIDE + kk + 4 + tig]);
                af[mi][3] = __float_as_uint(sA[(mb + 8 + gid) * SA_STRIDE + kk + 4 + tig]);
            }
#pragma unroll
            for (int ni = 0; ni < 8; ni++) {
                int nb = warp_n * 64 + ni * 8;
                unsigned b0 = __float_as_uint(sB[(kk + tig)     * SB_STRIDE + nb + gid]);
                unsigned b1 = __float_as_uint(sB[(kk + 4 + tig) * SB_STRIDE + nb + gid]);
#pragma unroll
                for (int mi = 0; mi < 2; mi++) {
                    asm volatile(
                        "mma.sync.aligned.m16n8k8.row.col.f32.tf32.tf32.f32 "
                        "{%0,%1,%2,%3}, {%4,%5,%6,%7}, {%8,%9}, {%0,%1,%2,%3};\n"
                        : "+f"(acc[mi][ni][0]), "+f"(acc[mi][ni][1]),
                          "+f"(acc[mi][ni][2]), "+f"(acc[mi][ni][3])
                        : "r"(af[mi][0]), "r"(af[mi][1]), "r"(af[mi][2]), "r"(af[mi][3]),
                          "r"(b0), "r"(b1));
                }
            }
        }
        __syncthreads();
    }

    // store C
#pragma unroll
    for (int mi = 0; mi < 2; mi++) {
        int row0 = bm0 + warp_m * 32 + mi * 16 + gid;
#pragma unroll
        for (int ni = 0; ni < 8; ni++) {
            int col = bn0 + warp_n * 64 + ni * 8 + 2 * tig;
            if (row0 < N_NODES)
                *(float2*)&g_h1[(size_t)row0 * F_HID + col] =
                    make_float2(acc[mi][ni][0], acc[mi][ni][1]);
            if (row0 + 8 < N_NODES)
                *(float2*)&g_h1[(size_t)(row0 + 8) * F_HID + col] =
                    make_float2(acc[mi][ni][2], acc[mi][ni][3]);
        }
    }
}

// ------------- Aggregation L1 (+bias,+relu) fused with GEMM2 ------------------
// One warp per node (4 nodes sequentially per warp, 32 nodes per block).
// a1 row stays in registers (2x float4 per lane); h2 = a1 @ W2 via shfl
// broadcast against W2 staged in smem. g_a1 eliminated.
__global__ void __launch_bounds__(256)
k_agg1_gemm2(const float* __restrict__ b1, const float* __restrict__ W2) {
    __shared__ float sW[F_HID * N_CLASS];   // 41984 B
    for (int i = threadIdx.x; i < F_HID * N_CLASS; i += blockDim.x)
        sW[i] = W2[i];
    __syncthreads();

    int lane = threadIdx.x & 31;
    int wid  = threadIdx.x >> 5;
    bool hi  = lane < (N_CLASS - 32);

    float4 bias0 = *(const float4*)&b1[4 * lane];
    float4 bias1 = *(const float4*)&b1[F_HID / 2 + 4 * lane];

#pragma unroll 1
    for (int i = 0; i < 4; i++) {
        int d = blockIdx.x * 32 + wid * 4 + i;
        if (d >= N_NODES) return;

        int start = g_rowptr[d];
        int len   = g_cursor[d] - start;
        float dd  = g_dinv[d];

        float4 acc0 = make_float4(0.f, 0.f, 0.f, 0.f);
        float4 acc1 = make_float4(0.f, 0.f, 0.f, 0.f);

        const float4* __restrict__ h1v = (const float4*)g_h1;
        for (int e = 0; e < len; e++) {
            int   s  = g_srcs[start + e];
            float w  = g_wsrc[start + e] * dd;
            float4 r0 = __ldg(&h1v[(size_t)s * 64 + lane]);
            float4 r1 = __ldg(&h1v[(size_t)s * 64 + 32 + lane]);
            acc0.x += w * r0.x; acc0.y += w * r0.y; acc0.z += w * r0.z; acc0.w += w * r0.w;
            acc1.x += w * r1.x; acc1.y += w * r1.y; acc1.z += w * r1.z; acc1.w += w * r1.w;
        }
        // self loop
        {
            float w = dd * dd;
            float4 r0 = h1v[(size_t)d * 64 + lane];
            float4 r1 = h1v[(size_t)d * 64 + 32 + lane];
            acc0.x += w * r0.x; acc0.y += w * r0.y; acc0.z += w * r0.z; acc0.w += w * r0.w;
            acc1.x += w * r1.x; acc1.y += w * r1.y; acc1.z += w * r1.z; acc1.w += w * r1.w;
        }
        // bias + relu
        acc0.x = fmaxf(acc0.x + bias0.x, 0.f);
        acc0.y = fmaxf(acc0.y + bias0.y, 0.f);
        acc0.z = fmaxf(acc0.z + bias0.z, 0.f);
        acc0.w = fmaxf(acc0.w + bias0.w, 0.f);
        acc1.x = fmaxf(acc1.x + bias1.x, 0.f);
        acc1.y = fmaxf(acc1.y + bias1.y, 0.f);
        acc1.z = fmaxf(acc1.z + bias1.z, 0.f);
        acc1.w = fmaxf(acc1.w + bias1.w, 0.f);

        // h2 = a1 @ W2  (shfl broadcast; lane owns class col `lane` and `lane+32`)
        float h0 = 0.f, h1c = 0.f;
#pragma unroll
        for (int g = 0; g < 2; g++) {
            float4 v = g ? acc1 : acc0;
#pragma unroll 8
            for (int sl = 0; sl < 32; sl++) {
                float a0 = __shfl_sync(0xffffffffu, v.x, sl);
                float a1 = __shfl_sync(0xffffffffu, v.y, sl);
                float a2 = __shfl_sync(0xffffffffu, v.z, sl);
                float a3 = __shfl_sync(0xffffffffu, v.w, sl);
                int kb = g * (F_HID / 2) + sl * 4;
                const float* w0 = &sW[(kb + 0) * N_CLASS];
                const float* w1 = &sW[(kb + 1) * N_CLASS];
                const float* w2 = &sW[(kb + 2) * N_CLASS];
                const float* w3 = &sW[(kb + 3) * N_CLASS];
                h0 += a0 * w0[lane] + a1 * w1[lane] + a2 * w2[lane] + a3 * w3[lane];
                if (hi)
                    h1c += a0 * w0[lane + 32] + a1 * w1[lane + 32]
                         + a2 * w2[lane + 32] + a3 * w3[lane + 32];
            }
        }
        g_h2[(size_t)d * N_CLASS + lane] = h0;
        if (hi) g_h2[(size_t)d * N_CLASS + 32 + lane] = h1c;
    }
}

// ---------------- Aggregation L2 + bias + log_softmax -------------------------
__global__ void k_agg2_softmax(const float* __restrict__ b2, float* __restrict__ out) {
    int warp = (blockIdx.x * blockDim.x + threadIdx.x) >> 5;
    int lane = threadIdx.x & 31;
    if (warp >= N_NODES) return;
    int d = warp;
    int start = g_rowptr[d];
    int len   = g_cursor[d] - start;
    float dd  = g_dinv[d];
    bool hi   = lane < (N_CLASS - 32);

    float acc0 = 0.f, acc1 = 0.f;
    for (int e = 0; e < len; e++) {
        int   s = g_srcs[start + e];
        float w = g_wsrc[start + e] * dd;
        const float* row = &g_h2[(size_t)s * N_CLASS];
        acc0 += w * __ldg(&row[lane]);
        if (hi) acc1 += w * __ldg(&row[lane + 32]);
    }
    const float* rowd = &g_h2[(size_t)d * N_CLASS];
    float wd = dd * dd;
    float v0 = acc0 + wd * rowd[lane] + b2[lane];
    float v1 = hi ? (acc1 + wd * rowd[lane + 32] + b2[lane + 32]) : -1e30f;

    float m = fmaxf(v0, v1);
#pragma unroll
    for (int o = 16; o > 0; o >>= 1) m = fmaxf(m, __shfl_xor_sync(0xffffffffu, m, o));
    float se = expf(v0 - m) + (hi ? expf(v1 - m) : 0.f);
#pragma unroll
    for (int o = 16; o > 0; o >>= 1) se += __shfl_xor_sync(0xffffffffu, se, o);
    float lse = m + logf(se);

    out[(size_t)d * N_CLASS + lane] = v0 - lse;
    if (hi) out[(size_t)d * N_CLASS + 32 + lane] = v1 - lse;
}

// ---------------- launch -----------------------------------------------------
extern "C" void kernel_launch(void* const* d_in, const int* in_sizes, int n_in,
                              void* d_out, int out_size) {
    const float* x  = (const float*)d_in[0];
    const void*  ei = d_in[1];                 // int32 or int64, detected on device
    const float* W1 = (const float*)d_in[2];
    const float* b1 = (const float*)d_in[3];
    const float* W2 = (const float*)d_in[4];
    const float* b2 = (const float*)d_in[5];
    float* out = (float*)d_out;

    // CSR build (with edge-dtype detection)
    k_zero_cnt<<<(N_NODES + 255) / 256, 256>>>();
    k_detect<<<(N_EDGES + 255) / 256, 256>>>((const int*)ei);
    k_count<<<(N_EDGES + 255) / 256, 256>>>(ei);
    k_scan_block<<<N_SCAN_BLK, SCAN_B>>>();
    k_scan_sums<<<1, 1>>>();
    k_scan_finish<<<(N_NODES + 255) / 256, 256>>>();
    k_scatter<<<(N_EDGES + 255) / 256, 256>>>(ei);

    // layer 1: tf32 tensor-core GEMM
    {
        dim3 grid((N_NODES + G1_BM - 1) / G1_BM, F_HID / G1_BN);
        k_gemm1_tf32<<<grid, 256>>>(x, W1);
    }
    // agg1 + bias + relu + GEMM2 fused
    k_agg1_gemm2<<<(N_NODES + 31) / 32, 256>>>(b1, W2);

    // agg2 + bias + log_softmax
    k_agg2_softmax<<<(N_NODES * 32 + 255) / 256, 256>>>(b2, out);
}